// round 12
// baseline (speedup 1.0000x reference)
#include <cuda_runtime.h>
#include <math.h>

#define BB 4
#define NN 8192
#define KK 32
#define DD 64
#define TPB 256
#define NBLK 32      // blocks per batch: NBLK*TPB == NN (numerically load-bearing)

// ---------------- persistent device state (no runtime allocs) ---------------
__device__ float g_C[2][BB][KK*DD];
__device__ float g_CC[2][BB][KK];
__device__ float g_part[BB][NBLK][KK*DD];    // per-block weighted sums
__device__ float g_partw[BB][NBLK][KK];      // per-block weight sums
__device__ unsigned g_cnt[BB];
__device__ unsigned g_ass[BB][NN];           // tie bitmask per point
__device__ float g_Dt[BB][KK][NN];           // final distances, transposed
__device__ unsigned long long g_repmin[BB][KK];
__device__ float g_objp[BB][NBLK];           // per-block obj partials
__device__ unsigned short g_perm[NN];

// ---------------- threefry2x32-20 -------------------------------------------
__device__ __forceinline__ unsigned rotl32(unsigned v, int r) {
    return (v << r) | (v >> (32 - r));
}

__device__ __forceinline__ void tf2x32(unsigned k0, unsigned k1,
                                       unsigned x0, unsigned x1,
                                       unsigned &o0, unsigned &o1)
{
    unsigned k2 = k0 ^ k1 ^ 0x1BD11BDAu;
    x0 += k0; x1 += k1;
    x0+=x1; x1=rotl32(x1,13); x1^=x0;
    x0+=x1; x1=rotl32(x1,15); x1^=x0;
    x0+=x1; x1=rotl32(x1,26); x1^=x0;
    x0+=x1; x1=rotl32(x1, 6); x1^=x0;
    x0+=k1; x1+=k2+1u;
    x0+=x1; x1=rotl32(x1,17); x1^=x0;
    x0+=x1; x1=rotl32(x1,29); x1^=x0;
    x0+=x1; x1=rotl32(x1,16); x1^=x0;
    x0+=x1; x1=rotl32(x1,24); x1^=x0;
    x0+=k2; x1+=k0+2u;
    x0+=x1; x1=rotl32(x1,13); x1^=x0;
    x0+=x1; x1=rotl32(x1,15); x1^=x0;
    x0+=x1; x1=rotl32(x1,26); x1^=x0;
    x0+=x1; x1=rotl32(x1, 6); x1^=x0;
    x0+=k0; x1+=k1+3u;
    x0+=x1; x1=rotl32(x1,17); x1^=x0;
    x0+=x1; x1=rotl32(x1,29); x1^=x0;
    x0+=x1; x1=rotl32(x1,16); x1^=x0;
    x0+=x1; x1=rotl32(x1,24); x1^=x0;
    x0+=k1; x1+=k2+4u;
    x0+=x1; x1=rotl32(x1,13); x1^=x0;
    x0+=x1; x1=rotl32(x1,15); x1^=x0;
    x0+=x1; x1=rotl32(x1,26); x1^=x0;
    x0+=x1; x1=rotl32(x1, 6); x1^=x0;
    x0+=k2; x1+=k0+5u;
    o0 = x0; o1 = x1;
}

// stable-equivalent bitonic sort on (key,pos); 8192 elems, 1024 threads
__device__ void bitonic8192(unsigned* key, unsigned short* pos, int tid)
{
    for (unsigned size = 2; size <= NN; size <<= 1) {
        for (unsigned stride = size >> 1; stride > 0; stride >>= 1) {
            __syncthreads();
            for (unsigned v = tid; v < NN / 2; v += 1024u) {
                unsigned i = (v << 1) - (v & (stride - 1));
                unsigned j = i + stride;
                unsigned ka = key[i], kb = key[j];
                unsigned short pa = pos[i], pb = pos[j];
                bool agtb = (ka > kb) || (ka == kb && pa > pb);
                bool up = ((i & size) == 0);
                if (agtb == up) {
                    key[i] = kb; key[j] = ka;
                    pos[i] = pb; pos[j] = pa;
                }
            }
        }
    }
    __syncthreads();
}

// ---------------- init: permutation + C0 + state reset ----------------------
__global__ __launch_bounds__(1024) void init_kernel(const float* __restrict__ E)
{
    __shared__ unsigned        skey[NN];
    __shared__ unsigned short  spos[NN];
    const int tid = threadIdx.x;
    const int nth = 1024;

    unsigned ki0, ki1, nk0, nk1, s10, s11, s20, s21;
    tf2x32(0u, 42u, 0u, 0u, ki0, ki1);
    tf2x32(ki0, ki1, 0u, 0u, nk0, nk1);
    tf2x32(ki0, ki1, 0u, 1u, s10, s11);
    tf2x32(nk0, nk1, 0u, 1u, s20, s21);

    for (int i = tid; i < NN; i += nth) {
        unsigned o0, o1; tf2x32(s10, s11, 0u, (unsigned)i, o0, o1);
        skey[i] = o0 ^ o1; spos[i] = (unsigned short)i;
    }
    bitonic8192(skey, spos, tid);
    for (int i = tid; i < NN; i += nth) g_perm[i] = spos[i];
    __syncthreads();

    for (int i = tid; i < NN; i += nth) {
        unsigned o0, o1; tf2x32(s20, s21, 0u, (unsigned)i, o0, o1);
        skey[i] = o0 ^ o1; spos[i] = (unsigned short)i;
    }
    bitonic8192(skey, spos, tid);

    for (int i = tid; i < BB*KK*DD; i += nth) {
        int d = i & 63, k = (i >> 6) & 31, b = i >> 11;
        int sel = (int)g_perm[(int)spos[k]];
        g_C[0][b][k*DD + d] = E[((size_t)b*NN + sel)*DD + d];
    }
    for (int i = tid; i < BB*KK; i += nth) {
        int b = i >> 5, k = i & 31;
        g_repmin[b][k] = 0xFFFFFFFFFFFFFFFFull;
    }
    if (tid < BB) g_cnt[tid] = 0u;
    __syncthreads();
    for (int i = tid; i < BB*KK; i += nth) {
        int b = i >> 5, k = i & 31;
        float s = 0.f;
        for (int d = 0; d < DD; d++) { float c = g_C[0][b][k*DD + d]; s += c*c; }
        g_CC[0][b][k] = s;
    }
}

// ------ one k-means iteration (r11 body + fused prefetched tail reduce) -----
__global__ __launch_bounds__(TPB) void iter_kernel(const float* __restrict__ E,
                                                   const float* __restrict__ LW,
                                                   int p)
{
    const int b   = blockIdx.y;
    const int blk = blockIdx.x;
    const int tid = threadIdx.x;
    const int n   = blk * TPB + tid;
    const int lane = tid & 31, warp = tid >> 5;
    const int q   = p ^ 1;

    __shared__ float    sC[KK*DD];              // reused as c^2 scratch in tail
    __shared__ float    sCC[KK];
    __shared__ float    sW[TPB];
    __shared__ float    sAW[KK];
    __shared__ unsigned smask[KK][TPB/32];
    __shared__ bool     sLast;

    for (int i = tid; i < KK*DD; i += TPB) sC[i] = g_C[p][b][i];
    if (tid < KK) sCC[tid] = g_CC[p][b][tid];
    __syncthreads();

    // weight early: MUFU overlaps the FMA-heavy distance phase
    sW[tid] = expf(LW[(size_t)b*NN + n]);

    float x[DD];
    float xx = 0.f;
    const float4* xp = (const float4*)(E + ((size_t)b*NN + n)*DD);
    #pragma unroll
    for (int i = 0; i < DD/4; i++) {
        float4 v = xp[i];
        x[4*i] = v.x; x[4*i+1] = v.y; x[4*i+2] = v.z; x[4*i+3] = v.w;
        xx += v.x*v.x + v.y*v.y + v.z*v.z + v.w*v.w;
    }

    // distance loop — scalar chains verbatim r2/r11 (partial unroll 4)
    float dist[KK];
    float mind = 3.4e38f;
    #pragma unroll 4
    for (int k = 0; k < KK; k++) {
        float a0 = 0.f, a1 = 0.f, a2 = 0.f, a3 = 0.f;
        const float4* cp = (const float4*)(sC + k*DD);
        #pragma unroll
        for (int i = 0; i < DD/4; i++) {
            float4 c4 = cp[i];
            a0 += x[4*i]   * c4.x;
            a1 += x[4*i+1] * c4.y;
            a2 += x[4*i+2] * c4.z;
            a3 += x[4*i+3] * c4.w;
        }
        float dd = sCC[k] + xx - 2.f * ((a0 + a1) + (a2 + a3));
        dist[k] = dd;
        mind = fminf(mind, dd);
    }
    unsigned bits = 0u;
    #pragma unroll
    for (int k = 0; k < KK; k++)
        if (fabsf(dist[k] - mind) < 1e-8f) bits |= (1u << k);
    g_ass[b][n] = bits;

    #pragma unroll
    for (int k = 0; k < KK; k++) {
        unsigned m = __ballot_sync(0xffffffffu, (bits >> k) & 1u);
        if (lane == 0) smask[k][warp] = m;
    }
    __syncthreads();

    // deterministic accumulation: thread t owns (k = t>>3, dims d0..d0+7)
    // chains verbatim r2 (points ascending n)
    {
        const int k  = tid >> 3;
        const int d0 = (tid & 7) * 8;
        float acc[8] = {0,0,0,0,0,0,0,0};
        float wsum = 0.f;
        const float* Eb = E + (((size_t)b*NN + (size_t)blk*TPB)*DD + d0);
        #pragma unroll
        for (int wp = 0; wp < TPB/32; wp++) {
            unsigned m = smask[k][wp];
            while (m) {
                int l = __ffs(m) - 1; m &= m - 1;
                int nn = wp*32 + l;
                float wv = sW[nn];
                const float4* ep = (const float4*)(Eb + (size_t)nn*DD);
                float4 e0 = ep[0], e1 = ep[1];
                acc[0] += wv*e0.x; acc[1] += wv*e0.y; acc[2] += wv*e0.z; acc[3] += wv*e0.w;
                acc[4] += wv*e1.x; acc[5] += wv*e1.y; acc[6] += wv*e1.z; acc[7] += wv*e1.w;
                wsum += wv;
            }
        }
        float* pp = &g_part[b][blk][k*DD + d0];
        ((float4*)pp)[0] = make_float4(acc[0], acc[1], acc[2], acc[3]);
        ((float4*)pp)[1] = make_float4(acc[4], acc[5], acc[6], acc[7]);
        if ((tid & 7) == 0) g_partw[b][blk][k] = wsum;
    }

    __threadfence();
    __syncthreads();
    if (tid == 0) sLast = (atomicAdd(&g_cnt[b], 1u) == NBLK - 1);
    __syncthreads();
    if (!sLast) return;

    // ---- last block for batch b: prefetched cross-block reduce (MLP=32) ----
    // per-element scalar sums over blk 0..31 ascending — exact reduce_kernel
    // chain order (proven bit-safe in rounds 8/9).
    __threadfence();
    if (tid < KK) {
        float v[NBLK];
        #pragma unroll
        for (int j = 0; j < NBLK; j++) v[j] = __ldcg(&g_partw[b][j][tid]);
        float ws = 0.f;
        #pragma unroll
        for (int j = 0; j < NBLK; j++) ws += v[j];
        sAW[tid] = fmaxf(ws, 1e-12f);
    }
    __syncthreads();
    #pragma unroll
    for (int r = 0; r < (KK*DD)/TPB; r++) {        // 8 scalar elems per thread
        const int e = r*TPB + tid;
        float v[NBLK];
        #pragma unroll
        for (int j = 0; j < NBLK; j++) v[j] = __ldcg(&g_part[b][j][e]);
        float s = 0.f;
        #pragma unroll
        for (int j = 0; j < NBLK; j++) s += v[j];
        float c = s / sAW[e >> 6];
        g_C[q][b][e] = c;
        sC[e] = c * c;
    }
    __syncthreads();
    if (tid < KK) {
        float cc = 0.f;
        #pragma unroll
        for (int d = 0; d < DD; d++) cc += sC[tid*DD + d];
        g_CC[q][b][tid] = cc;
    }
    if (tid == 0) g_cnt[b] = 0u;
}

// ---------------- final pass 1: Dt, obj partial, rep argmin, ass out --------
__global__ __launch_bounds__(TPB) void final1_kernel(const float* __restrict__ E,
                                                     float* __restrict__ out)
{
    const int b   = blockIdx.y;
    const int blk = blockIdx.x;
    const int tid = threadIdx.x;
    const int n   = blk * TPB + tid;

    __shared__ float sC[KK*DD];
    __shared__ float sCC[KK];
    __shared__ unsigned long long srep[KK];
    __shared__ float sred[TPB/32];

    for (int i = tid; i < KK*DD; i += TPB) sC[i] = g_C[0][b][i];
    if (tid < KK) { sCC[tid] = g_CC[0][b][tid]; srep[tid] = 0xFFFFFFFFFFFFFFFFull; }
    __syncthreads();

    float x[DD];
    float xx = 0.f;
    const float4* xp = (const float4*)(E + ((size_t)b*NN + n)*DD);
    #pragma unroll
    for (int i = 0; i < DD/4; i++) {
        float4 v = xp[i];
        x[4*i] = v.x; x[4*i+1] = v.y; x[4*i+2] = v.z; x[4*i+3] = v.w;
        xx += v.x*v.x + v.y*v.y + v.z*v.z + v.w*v.w;
    }

    float dist[KK];
    float mind = 3.4e38f;
    #pragma unroll 4
    for (int k = 0; k < KK; k++) {
        float a0 = 0.f, a1 = 0.f, a2 = 0.f, a3 = 0.f;
        const float4* cp = (const float4*)(sC + k*DD);
        #pragma unroll
        for (int i = 0; i < DD/4; i++) {
            float4 c4 = cp[i];
            a0 += x[4*i]   * c4.x;
            a1 += x[4*i+1] * c4.y;
            a2 += x[4*i+2] * c4.z;
            a3 += x[4*i+3] * c4.w;
        }
        float dd = sCC[k] + xx - 2.f * ((a0 + a1) + (a2 + a3));
        dist[k] = dd;
        mind = fminf(mind, dd);
    }

    #pragma unroll
    for (int k = 0; k < KK; k++) {
        g_Dt[b][k][n] = dist[k];
        unsigned u = __float_as_uint(dist[k]);
        u = (u & 0x80000000u) ? ~u : (u | 0x80000000u);
        unsigned long long keyv = ((unsigned long long)u << 32) | (unsigned)n;
        atomicMin(&srep[k], keyv);
    }

    // obj partial: fixed-order warp shuffle + in-order warp combine
    float s = mind;
    #pragma unroll
    for (int o = 16; o; o >>= 1) s += __shfl_down_sync(0xffffffffu, s, o);
    if ((tid & 31) == 0) sred[tid >> 5] = s;
    __syncthreads();
    if (tid == 0) {
        float t = 0.f;
        #pragma unroll
        for (int w = 0; w < TPB/32; w++) t += sred[w];
        g_objp[b][blk] = t;
    }
    if (tid < KK) atomicMin(&g_repmin[b][tid], srep[tid]);

    // expand assignment bitmask -> float matrix
    unsigned bits = g_ass[b][n];
    float* ob = out + ((size_t)b*NN + n) * KK;
    #pragma unroll
    for (int k4 = 0; k4 < KK; k4 += 4) {
        float4 v;
        v.x = (bits >> (k4    )) & 1u ? 1.f : 0.f;
        v.y = (bits >> (k4 + 1)) & 1u ? 1.f : 0.f;
        v.z = (bits >> (k4 + 2)) & 1u ? 1.f : 0.f;
        v.w = (bits >> (k4 + 3)) & 1u ? 1.f : 0.f;
        ((float4*)ob)[k4 >> 2] = v;
    }
}

// ---------------- final pass 2: rep, rep_idx, C, obj outputs ----------------
#define F2T 512
__global__ __launch_bounds__(F2T) void final2_kernel(const float* __restrict__ E,
                                                     float* __restrict__ out)
{
    const int b = blockIdx.y, k = blockIdx.x, tid = threadIdx.x;
    const int d = tid & 63;          // dim
    const int st = tid >> 6;         // stripe 0..7
    __shared__ float spart[8][DD];
    __shared__ int   scnt[8];

    unsigned long long packed = g_repmin[b][k];
    unsigned enc = (unsigned)(packed >> 32);
    unsigned idx = (unsigned)(packed & 0xFFFFFFFFu);
    unsigned u = (enc & 0x80000000u) ? (enc & 0x7FFFFFFFu) : ~enc;
    float mind = __uint_as_float(u);

    // strided scan; each stripe accumulates in increasing n order
    float s = 0.f;
    int cnt = 0;
    const float* Dk = &g_Dt[b][k][0];
    for (int n = st; n < NN; n += 8) {
        float dv = Dk[n];
        if (fabsf(dv - mind) < 1e-8f) {
            s += E[((size_t)b*NN + n)*DD + d];
            cnt++;
        }
    }
    spart[st][d] = s;
    if (d == 0) scnt[st] = cnt;
    __syncthreads();

    if (tid < DD) {
        float tot = 0.f;
        int ctot = 0;
        #pragma unroll
        for (int i = 0; i < 8; i++) { tot += spart[i][tid]; ctot += scnt[i]; }
        float denom = fmaxf((float)ctot, 0.001f);

        const size_t CB = (size_t)BB*NN*KK;
        out[CB + (size_t)(b*KK + k)*DD + tid] = g_C[0][b][k*DD + tid];
        out[CB + (size_t)BB*KK*DD + (size_t)(b*KK + k)*DD + tid] = tot / denom;
        if (tid == 0)
            out[CB + 2*(size_t)BB*KK*DD + b*KK + k] = (float)idx;
        if (tid == 0 && k == 0) {
            float o = 0.f;
            #pragma unroll
            for (int blk = 0; blk < NBLK; blk++) o += g_objp[b][blk];
            out[CB + 2*(size_t)BB*KK*DD + BB*KK + b] = o / (float)NN;
        }
    }
}

// ---------------- launch ----------------------------------------------------
extern "C" void kernel_launch(void* const* d_in, const int* in_sizes, int n_in,
                              void* d_out, int out_size)
{
    const float* E  = (const float*)d_in[0];
    const float* LW = (const float*)d_in[1];
    if (n_in >= 2 && in_sizes[0] == BB*NN) {
        E  = (const float*)d_in[1];
        LW = (const float*)d_in[0];
    }
    float* out = (float*)d_out;

    init_kernel<<<1, 1024>>>(E);
    for (int t = 0; t < 30; t++)
        iter_kernel<<<dim3(NBLK, BB), TPB>>>(E, LW, t & 1);
    final1_kernel<<<dim3(NBLK, BB), TPB>>>(E, out);
    final2_kernel<<<dim3(KK, BB), F2T>>>(E, out);
    (void)out_size;
}

// round 13
// speedup vs baseline: 1.4270x; 1.4270x over previous
#include <cuda_runtime.h>
#include <math.h>

#define BB 4
#define NN 8192
#define KK 32
#define DD 64
#define TPB 256
#define NBLK 32      // blocks per batch: NBLK*TPB == NN

// ---------------- persistent device state (no runtime allocs) ---------------
__device__ float g_C[2][BB][KK*DD];
__device__ float g_CC[2][BB][KK];
__device__ float g_part[BB][NBLK][KK*DD];    // per-block weighted sums
__device__ float g_partw[BB][NBLK][KK];      // per-block weight sums
__device__ unsigned g_ass[BB][NN];           // tie bitmask per point
__device__ float g_Dt[BB][KK][NN];           // final distances, transposed
__device__ unsigned long long g_repmin[BB][KK];
__device__ float g_objp[BB][NBLK];           // per-block obj partials
__device__ unsigned short g_perm[NN];

// ---------------- threefry2x32-20 -------------------------------------------
__device__ __forceinline__ unsigned rotl32(unsigned v, int r) {
    return (v << r) | (v >> (32 - r));
}

__device__ __forceinline__ void tf2x32(unsigned k0, unsigned k1,
                                       unsigned x0, unsigned x1,
                                       unsigned &o0, unsigned &o1)
{
    unsigned k2 = k0 ^ k1 ^ 0x1BD11BDAu;
    x0 += k0; x1 += k1;
    x0+=x1; x1=rotl32(x1,13); x1^=x0;
    x0+=x1; x1=rotl32(x1,15); x1^=x0;
    x0+=x1; x1=rotl32(x1,26); x1^=x0;
    x0+=x1; x1=rotl32(x1, 6); x1^=x0;
    x0+=k1; x1+=k2+1u;
    x0+=x1; x1=rotl32(x1,17); x1^=x0;
    x0+=x1; x1=rotl32(x1,29); x1^=x0;
    x0+=x1; x1=rotl32(x1,16); x1^=x0;
    x0+=x1; x1=rotl32(x1,24); x1^=x0;
    x0+=k2; x1+=k0+2u;
    x0+=x1; x1=rotl32(x1,13); x1^=x0;
    x0+=x1; x1=rotl32(x1,15); x1^=x0;
    x0+=x1; x1=rotl32(x1,26); x1^=x0;
    x0+=x1; x1=rotl32(x1, 6); x1^=x0;
    x0+=k0; x1+=k1+3u;
    x0+=x1; x1=rotl32(x1,17); x1^=x0;
    x0+=x1; x1=rotl32(x1,29); x1^=x0;
    x0+=x1; x1=rotl32(x1,16); x1^=x0;
    x0+=x1; x1=rotl32(x1,24); x1^=x0;
    x0+=k1; x1+=k2+4u;
    x0+=x1; x1=rotl32(x1,13); x1^=x0;
    x0+=x1; x1=rotl32(x1,15); x1^=x0;
    x0+=x1; x1=rotl32(x1,26); x1^=x0;
    x0+=x1; x1=rotl32(x1, 6); x1^=x0;
    x0+=k2; x1+=k0+5u;
    o0 = x0; o1 = x1;
}

// stable-equivalent bitonic sort on (key,pos); 8192 elems, 1024 threads
__device__ void bitonic8192(unsigned* key, unsigned short* pos, int tid)
{
    for (unsigned size = 2; size <= NN; size <<= 1) {
        for (unsigned stride = size >> 1; stride > 0; stride >>= 1) {
            __syncthreads();
            for (unsigned v = tid; v < NN / 2; v += 1024u) {
                unsigned i = (v << 1) - (v & (stride - 1));
                unsigned j = i + stride;
                unsigned ka = key[i], kb = key[j];
                unsigned short pa = pos[i], pb = pos[j];
                bool agtb = (ka > kb) || (ka == kb && pa > pb);
                bool up = ((i & size) == 0);
                if (agtb == up) {
                    key[i] = kb; key[j] = ka;
                    pos[i] = pb; pos[j] = pa;
                }
            }
        }
    }
    __syncthreads();
}

// ---------------- init: permutation + C0 + state reset ----------------------
__global__ __launch_bounds__(1024) void init_kernel(const float* __restrict__ E)
{
    __shared__ unsigned        skey[NN];
    __shared__ unsigned short  spos[NN];
    const int tid = threadIdx.x;
    const int nth = 1024;

    unsigned ki0, ki1, nk0, nk1, s10, s11, s20, s21;
    tf2x32(0u, 42u, 0u, 0u, ki0, ki1);
    tf2x32(ki0, ki1, 0u, 0u, nk0, nk1);
    tf2x32(ki0, ki1, 0u, 1u, s10, s11);
    tf2x32(nk0, nk1, 0u, 1u, s20, s21);

    for (int i = tid; i < NN; i += nth) {
        unsigned o0, o1; tf2x32(s10, s11, 0u, (unsigned)i, o0, o1);
        skey[i] = o0 ^ o1; spos[i] = (unsigned short)i;
    }
    bitonic8192(skey, spos, tid);
    for (int i = tid; i < NN; i += nth) g_perm[i] = spos[i];
    __syncthreads();

    for (int i = tid; i < NN; i += nth) {
        unsigned o0, o1; tf2x32(s20, s21, 0u, (unsigned)i, o0, o1);
        skey[i] = o0 ^ o1; spos[i] = (unsigned short)i;
    }
    bitonic8192(skey, spos, tid);

    for (int i = tid; i < BB*KK*DD; i += nth) {
        int d = i & 63, k = (i >> 6) & 31, b = i >> 11;
        int sel = (int)g_perm[(int)spos[k]];
        g_C[0][b][k*DD + d] = E[((size_t)b*NN + sel)*DD + d];
    }
    for (int i = tid; i < BB*KK; i += nth) {
        int b = i >> 5, k = i & 31;
        g_repmin[b][k] = 0xFFFFFFFFFFFFFFFFull;
    }
    __syncthreads();
    for (int i = tid; i < BB*KK; i += nth) {
        int b = i >> 5, k = i & 31;
        float s = 0.f;
        for (int d = 0; d < DD; d++) { float c = g_C[0][b][k*DD + d]; s += c*c; }
        g_CC[0][b][k] = s;
    }
}

// ---------------- one k-means assignment + partial-sum pass (r2 verbatim) ---
__global__ __launch_bounds__(TPB) void iter_kernel(const float* __restrict__ E,
                                                   const float* __restrict__ LW,
                                                   int p)
{
    const int b   = blockIdx.y;
    const int blk = blockIdx.x;
    const int tid = threadIdx.x;
    const int n   = blk * TPB + tid;
    const int lane = tid & 31, warp = tid >> 5;

    __shared__ float    sC[KK*DD];
    __shared__ float    sCC[KK];
    __shared__ float    sW[TPB];
    __shared__ unsigned smask[KK][TPB/32];

    for (int i = tid; i < KK*DD; i += TPB) sC[i] = g_C[p][b][i];
    if (tid < KK) sCC[tid] = g_CC[p][b][tid];
    __syncthreads();

    float x[DD];
    float xx = 0.f;
    const float4* xp = (const float4*)(E + ((size_t)b*NN + n)*DD);
    #pragma unroll
    for (int i = 0; i < DD/4; i++) {
        float4 v = xp[i];
        x[4*i] = v.x; x[4*i+1] = v.y; x[4*i+2] = v.z; x[4*i+3] = v.w;
        xx += v.x*v.x + v.y*v.y + v.z*v.z + v.w*v.w;
    }

    float dist[KK];
    float mind = 3.4e38f;
    #pragma unroll
    for (int k = 0; k < KK; k++) {
        float a0 = 0.f, a1 = 0.f, a2 = 0.f, a3 = 0.f;
        const float4* cp = (const float4*)(sC + k*DD);
        #pragma unroll
        for (int i = 0; i < DD/4; i++) {
            float4 c4 = cp[i];
            a0 += x[4*i]   * c4.x;
            a1 += x[4*i+1] * c4.y;
            a2 += x[4*i+2] * c4.z;
            a3 += x[4*i+3] * c4.w;
        }
        float dd = sCC[k] + xx - 2.f * ((a0 + a1) + (a2 + a3));
        dist[k] = dd;
        mind = fminf(mind, dd);
    }
    unsigned bits = 0u;
    #pragma unroll
    for (int k = 0; k < KK; k++)
        if (fabsf(dist[k] - mind) < 1e-8f) bits |= (1u << k);
    g_ass[b][n] = bits;
    sW[tid] = expf(LW[(size_t)b*NN + n]);

    #pragma unroll
    for (int k = 0; k < KK; k++) {
        unsigned m = __ballot_sync(0xffffffffu, (bits >> k) & 1u);
        if (lane == 0) smask[k][warp] = m;
    }
    __syncthreads();

    // deterministic accumulation: thread t owns (k = t>>3, dims d0..d0+7)
    const int k  = tid >> 3;
    const int d0 = (tid & 7) * 8;
    float acc[8] = {0,0,0,0,0,0,0,0};
    float wsum = 0.f;
    const float* Eb = E + (((size_t)b*NN + (size_t)blk*TPB)*DD + d0);
    #pragma unroll
    for (int wp = 0; wp < TPB/32; wp++) {
        unsigned m = smask[k][wp];
        while (m) {
            int l = __ffs(m) - 1; m &= m - 1;
            int nn = wp*32 + l;
            float wv = sW[nn];
            const float4* ep = (const float4*)(Eb + (size_t)nn*DD);
            float4 e0 = ep[0], e1 = ep[1];
            acc[0] += wv*e0.x; acc[1] += wv*e0.y; acc[2] += wv*e0.z; acc[3] += wv*e0.w;
            acc[4] += wv*e1.x; acc[5] += wv*e1.y; acc[6] += wv*e1.z; acc[7] += wv*e1.w;
            wsum += wv;
        }
    }
    float* pp = &g_part[b][blk][k*DD + d0];
    ((float4*)pp)[0] = make_float4(acc[0], acc[1], acc[2], acc[3]);
    ((float4*)pp)[1] = make_float4(acc[4], acc[5], acc[6], acc[7]);
    if ((tid & 7) == 0) g_partw[b][blk][k] = wsum;
}

// ---------------- cross-block reduce: new C, CC (fixed order, r2 verbatim) --
__global__ __launch_bounds__(TPB) void reduce_kernel(int p)
{
    const int b   = blockIdx.y;
    const int r   = blockIdx.x;           // 8 blocks, 256 elems each
    const int tid = threadIdx.x;
    const int q   = p ^ 1;
    const int elem = r * TPB + tid;
    const int kloc = tid >> 6;            // 4 k's per block

    __shared__ float swk[4];
    __shared__ float sc2[TPB];

    float s = 0.f;
    #pragma unroll
    for (int blk = 0; blk < NBLK; blk++) s += g_part[b][blk][elem];

    if ((tid & 63) == 0) {
        int k = elem >> 6;
        float ws = 0.f;
        #pragma unroll
        for (int blk = 0; blk < NBLK; blk++) ws += g_partw[b][blk][k];
        swk[kloc] = fmaxf(ws, 1e-12f);
    }
    __syncthreads();
    float c = s / swk[kloc];
    g_C[q][b][elem] = c;
    sc2[tid] = c * c;
    __syncthreads();
    if (tid < 4) {
        float cc = 0.f;
        #pragma unroll
        for (int d = 0; d < DD; d++) cc += sc2[tid*DD + d];
        g_CC[q][b][r*4 + tid] = cc;
    }
}

// ---------------- final pass 1: Dt, obj partial, rep argmin, ass out --------
__global__ __launch_bounds__(TPB) void final1_kernel(const float* __restrict__ E,
                                                     float* __restrict__ out)
{
    const int b   = blockIdx.y;
    const int blk = blockIdx.x;
    const int tid = threadIdx.x;
    const int n   = blk * TPB + tid;

    __shared__ float sC[KK*DD];
    __shared__ float sCC[KK];
    __shared__ unsigned long long srep[KK];
    __shared__ float sred[TPB/32];

    for (int i = tid; i < KK*DD; i += TPB) sC[i] = g_C[0][b][i];
    if (tid < KK) { sCC[tid] = g_CC[0][b][tid]; srep[tid] = 0xFFFFFFFFFFFFFFFFull; }
    __syncthreads();

    float x[DD];
    float xx = 0.f;
    const float4* xp = (const float4*)(E + ((size_t)b*NN + n)*DD);
    #pragma unroll
    for (int i = 0; i < DD/4; i++) {
        float4 v = xp[i];
        x[4*i] = v.x; x[4*i+1] = v.y; x[4*i+2] = v.z; x[4*i+3] = v.w;
        xx += v.x*v.x + v.y*v.y + v.z*v.z + v.w*v.w;
    }

    float dist[KK];
    float mind = 3.4e38f;
    #pragma unroll
    for (int k = 0; k < KK; k++) {
        float a0 = 0.f, a1 = 0.f, a2 = 0.f, a3 = 0.f;
        const float4* cp = (const float4*)(sC + k*DD);
        #pragma unroll
        for (int i = 0; i < DD/4; i++) {
            float4 c4 = cp[i];
            a0 += x[4*i]   * c4.x;
            a1 += x[4*i+1] * c4.y;
            a2 += x[4*i+2] * c4.z;
            a3 += x[4*i+3] * c4.w;
        }
        float dd = sCC[k] + xx - 2.f * ((a0 + a1) + (a2 + a3));
        dist[k] = dd;
        mind = fminf(mind, dd);
    }

    #pragma unroll
    for (int k = 0; k < KK; k++) {
        g_Dt[b][k][n] = dist[k];
        unsigned u = __float_as_uint(dist[k]);
        u = (u & 0x80000000u) ? ~u : (u | 0x80000000u);
        unsigned long long keyv = ((unsigned long long)u << 32) | (unsigned)n;
        atomicMin(&srep[k], keyv);
    }

    // obj partial: fixed-order warp shuffle + in-order warp combine
    float s = mind;
    #pragma unroll
    for (int o = 16; o; o >>= 1) s += __shfl_down_sync(0xffffffffu, s, o);
    if ((tid & 31) == 0) sred[tid >> 5] = s;
    __syncthreads();
    if (tid == 0) {
        float t = 0.f;
        #pragma unroll
        for (int w = 0; w < TPB/32; w++) t += sred[w];
        g_objp[b][blk] = t;
    }
    if (tid < KK) atomicMin(&g_repmin[b][tid], srep[tid]);

    // expand assignment bitmask -> float matrix
    unsigned bits = g_ass[b][n];
    float* ob = out + ((size_t)b*NN + n) * KK;
    #pragma unroll
    for (int k4 = 0; k4 < KK; k4 += 4) {
        float4 v;
        v.x = (bits >> (k4    )) & 1u ? 1.f : 0.f;
        v.y = (bits >> (k4 + 1)) & 1u ? 1.f : 0.f;
        v.z = (bits >> (k4 + 2)) & 1u ? 1.f : 0.f;
        v.w = (bits >> (k4 + 3)) & 1u ? 1.f : 0.f;
        ((float4*)ob)[k4 >> 2] = v;
    }
}

// ---------------- final pass 2: rep, rep_idx, C, obj outputs ----------------
// Restructured: cooperative mask scan (each Dt element read ONCE), warp-0
// ordered compaction, then 64 threads sum the matching E rows ascending-n.
#define F2T 512
__global__ __launch_bounds__(F2T) void final2_kernel(const float* __restrict__ E,
                                                     float* __restrict__ out)
{
    const int b = blockIdx.y, k = blockIdx.x, tid = threadIdx.x;

    __shared__ unsigned smk[F2T];    // 16-bit match masks
    __shared__ int      slist[64];   // ascending-n match indices
    __shared__ int      scount;

    unsigned long long packed = g_repmin[b][k];
    unsigned enc = (unsigned)(packed >> 32);
    unsigned idx = (unsigned)(packed & 0xFFFFFFFFu);
    unsigned u = (enc & 0x80000000u) ? (enc & 0x7FFFFFFFu) : ~enc;
    float mind = __uint_as_float(u);

    // phase 1: each thread scans 16 contiguous distances (coalesced, once)
    {
        const float* Dk = &g_Dt[b][k][tid * 16];
        unsigned m = 0u;
        #pragma unroll
        for (int j = 0; j < 16; j++)
            if (fabsf(Dk[j] - mind) < 1e-8f) m |= (1u << j);
        smk[tid] = m;
    }
    __syncthreads();

    // phase 2: warp 0 compacts set bits into ascending-n index list
    if (tid < 32) {
        unsigned mw[16];
        int cnt = 0;
        #pragma unroll
        for (int j = 0; j < 16; j++) {
            mw[j] = smk[tid*16 + j];
            cnt += __popc(mw[j]);
        }
        // exclusive prefix over lanes (ascending lane = ascending n)
        int off = cnt;
        #pragma unroll
        for (int o = 1; o < 32; o <<= 1) {
            int v = __shfl_up_sync(0xffffffffu, off, o);
            if ((tid & 31) >= o) off += v;
        }
        int total = __shfl_sync(0xffffffffu, off, 31);
        off -= cnt;                          // exclusive offset
        int pos = off;
        #pragma unroll
        for (int j = 0; j < 16; j++) {
            unsigned m = mw[j];
            while (m) {
                int l2 = __ffs(m) - 1; m &= m - 1;
                if (pos < 64) slist[pos] = (tid*16 + j)*16 + l2;
                pos++;
            }
        }
        if (tid == 31) scount = total;
    }
    __syncthreads();

    if (tid < DD) {
        int c = min(scount, 64);
        float denom = fmaxf((float)scount, 0.001f);
        float s = 0.f;
        for (int t = 0; t < c; t++)
            s += E[((size_t)b*NN + slist[t])*DD + tid];

        const size_t CB = (size_t)BB*NN*KK;
        out[CB + (size_t)(b*KK + k)*DD + tid] = g_C[0][b][k*DD + tid];
        out[CB + (size_t)BB*KK*DD + (size_t)(b*KK + k)*DD + tid] = s / denom;
        if (tid == 0)
            out[CB + 2*(size_t)BB*KK*DD + b*KK + k] = (float)idx;
        if (tid == 0 && k == 0) {
            float o = 0.f;
            #pragma unroll
            for (int blk = 0; blk < NBLK; blk++) o += g_objp[b][blk];
            out[CB + 2*(size_t)BB*KK*DD + BB*KK + b] = o / (float)NN;
        }
    }
}

// ---------------- launch ----------------------------------------------------
extern "C" void kernel_launch(void* const* d_in, const int* in_sizes, int n_in,
                              void* d_out, int out_size)
{
    const float* E  = (const float*)d_in[0];
    const float* LW = (const float*)d_in[1];
    if (n_in >= 2 && in_sizes[0] == BB*NN) {
        E  = (const float*)d_in[1];
        LW = (const float*)d_in[0];
    }
    float* out = (float*)d_out;

    init_kernel<<<1, 1024>>>(E);
    for (int t = 0; t < 30; t++) {
        iter_kernel<<<dim3(NBLK, BB), TPB>>>(E, LW, t & 1);
        reduce_kernel<<<dim3(8, BB), TPB>>>(t & 1);
    }
    final1_kernel<<<dim3(NBLK, BB), TPB>>>(E, out);
    final2_kernel<<<dim3(KK, BB), F2T>>>(E, out);
    (void)out_size;
}

// round 14
// speedup vs baseline: 1.4554x; 1.0199x over previous
#include <cuda_runtime.h>
#include <math.h>

#define BB 4
#define NN 8192
#define KK 32
#define DD 64
#define TPB 256
#define NBLK 32      // blocks per batch: NBLK*TPB == NN (numerically load-bearing)

// ---------------- persistent device state (no runtime allocs) ---------------
__device__ float g_C[BB][KK*DD];                // init + final C (buffer 0 only)
__device__ float g_CC[BB][KK];
__device__ float g_part[2][BB][NBLK][KK*DD];    // per-block weighted sums (dbl-buf)
__device__ float g_partw[2][BB][NBLK][KK];      // per-block weight sums  (dbl-buf)
__device__ unsigned g_ass[BB][NN];              // tie bitmask per point
__device__ float g_Dt[BB][KK][NN];              // final distances, transposed
__device__ unsigned long long g_repmin[BB][KK];
__device__ float g_objp[BB][NBLK];              // per-block obj partials
__device__ unsigned short g_perm[NN];

// ---------------- threefry2x32-20 -------------------------------------------
__device__ __forceinline__ unsigned rotl32(unsigned v, int r) {
    return (v << r) | (v >> (32 - r));
}

__device__ __forceinline__ void tf2x32(unsigned k0, unsigned k1,
                                       unsigned x0, unsigned x1,
                                       unsigned &o0, unsigned &o1)
{
    unsigned k2 = k0 ^ k1 ^ 0x1BD11BDAu;
    x0 += k0; x1 += k1;
    x0+=x1; x1=rotl32(x1,13); x1^=x0;
    x0+=x1; x1=rotl32(x1,15); x1^=x0;
    x0+=x1; x1=rotl32(x1,26); x1^=x0;
    x0+=x1; x1=rotl32(x1, 6); x1^=x0;
    x0+=k1; x1+=k2+1u;
    x0+=x1; x1=rotl32(x1,17); x1^=x0;
    x0+=x1; x1=rotl32(x1,29); x1^=x0;
    x0+=x1; x1=rotl32(x1,16); x1^=x0;
    x0+=x1; x1=rotl32(x1,24); x1^=x0;
    x0+=k2; x1+=k0+2u;
    x0+=x1; x1=rotl32(x1,13); x1^=x0;
    x0+=x1; x1=rotl32(x1,15); x1^=x0;
    x0+=x1; x1=rotl32(x1,26); x1^=x0;
    x0+=x1; x1=rotl32(x1, 6); x1^=x0;
    x0+=k0; x1+=k1+3u;
    x0+=x1; x1=rotl32(x1,17); x1^=x0;
    x0+=x1; x1=rotl32(x1,29); x1^=x0;
    x0+=x1; x1=rotl32(x1,16); x1^=x0;
    x0+=x1; x1=rotl32(x1,24); x1^=x0;
    x0+=k1; x1+=k2+4u;
    x0+=x1; x1=rotl32(x1,13); x1^=x0;
    x0+=x1; x1=rotl32(x1,15); x1^=x0;
    x0+=x1; x1=rotl32(x1,26); x1^=x0;
    x0+=x1; x1=rotl32(x1, 6); x1^=x0;
    x0+=k2; x1+=k0+5u;
    o0 = x0; o1 = x1;
}

// stable-equivalent bitonic sort on (key,pos); 8192 elems, 1024 threads
__device__ void bitonic8192(unsigned* key, unsigned short* pos, int tid)
{
    for (unsigned size = 2; size <= NN; size <<= 1) {
        for (unsigned stride = size >> 1; stride > 0; stride >>= 1) {
            __syncthreads();
            for (unsigned v = tid; v < NN / 2; v += 1024u) {
                unsigned i = (v << 1) - (v & (stride - 1));
                unsigned j = i + stride;
                unsigned ka = key[i], kb = key[j];
                unsigned short pa = pos[i], pb = pos[j];
                bool agtb = (ka > kb) || (ka == kb && pa > pb);
                bool up = ((i & size) == 0);
                if (agtb == up) {
                    key[i] = kb; key[j] = ka;
                    pos[i] = pb; pos[j] = pa;
                }
            }
        }
    }
    __syncthreads();
}

// ---------------- init: permutation + C0 + state reset ----------------------
__global__ __launch_bounds__(1024) void init_kernel(const float* __restrict__ E)
{
    __shared__ unsigned        skey[NN];
    __shared__ unsigned short  spos[NN];
    const int tid = threadIdx.x;
    const int nth = 1024;

    unsigned ki0, ki1, nk0, nk1, s10, s11, s20, s21;
    tf2x32(0u, 42u, 0u, 0u, ki0, ki1);
    tf2x32(ki0, ki1, 0u, 0u, nk0, nk1);
    tf2x32(ki0, ki1, 0u, 1u, s10, s11);
    tf2x32(nk0, nk1, 0u, 1u, s20, s21);

    for (int i = tid; i < NN; i += nth) {
        unsigned o0, o1; tf2x32(s10, s11, 0u, (unsigned)i, o0, o1);
        skey[i] = o0 ^ o1; spos[i] = (unsigned short)i;
    }
    bitonic8192(skey, spos, tid);
    for (int i = tid; i < NN; i += nth) g_perm[i] = spos[i];
    __syncthreads();

    for (int i = tid; i < NN; i += nth) {
        unsigned o0, o1; tf2x32(s20, s21, 0u, (unsigned)i, o0, o1);
        skey[i] = o0 ^ o1; spos[i] = (unsigned short)i;
    }
    bitonic8192(skey, spos, tid);

    for (int i = tid; i < BB*KK*DD; i += nth) {
        int d = i & 63, k = (i >> 6) & 31, b = i >> 11;
        int sel = (int)g_perm[(int)spos[k]];
        g_C[b][k*DD + d] = E[((size_t)b*NN + sel)*DD + d];
    }
    for (int i = tid; i < BB*KK; i += nth) {
        int b = i >> 5, k = i & 31;
        g_repmin[b][k] = 0xFFFFFFFFFFFFFFFFull;
    }
    __syncthreads();
    for (int i = tid; i < BB*KK; i += nth) {
        int b = i >> 5, k = i & 31;
        float s = 0.f;
        for (int d = 0; d < DD; d++) { float c = g_C[b][k*DD + d]; s += c*c; }
        g_CC[b][k] = s;
    }
}

// ---- prologue reduce: rebuild C,CC in smem from prev iter's partials -------
// Chains identical to the old reduce_kernel: per-element sums over blk 0..31
// ascending; w ascending; CC ascending-d of c^2.
__device__ __forceinline__ void prologue_reduce(int rd, int b, int tid,
                                                float* sC, float* sCC,
                                                float* sAW)
{
    if (tid < KK) {
        float v[NBLK];
        #pragma unroll
        for (int j = 0; j < NBLK; j++) v[j] = g_partw[rd][b][j][tid];
        float ws = 0.f;
        #pragma unroll
        for (int j = 0; j < NBLK; j++) ws += v[j];
        sAW[tid] = fmaxf(ws, 1e-12f);
    }
    __syncthreads();
    #pragma unroll
    for (int r = 0; r < (KK*DD)/TPB; r++) {
        const int e = r*TPB + tid;
        float v[NBLK];
        #pragma unroll
        for (int j = 0; j < NBLK; j++) v[j] = g_part[rd][b][j][e];
        float s = 0.f;
        #pragma unroll
        for (int j = 0; j < NBLK; j++) s += v[j];
        sC[e] = s / sAW[e >> 6];
    }
    __syncthreads();
    if (tid < KK) {
        float cc = 0.f;
        #pragma unroll
        for (int d = 0; d < DD; d++) { float c = sC[tid*DD + d]; cc += c*c; }
        sCC[tid] = cc;
    }
}

// ---------------- one k-means iteration (prologue reduce + r2 body) ---------
__global__ __launch_bounds__(TPB) void iter_kernel(const float* __restrict__ E,
                                                   const float* __restrict__ LW,
                                                   int rd, int wr, int first)
{
    const int b   = blockIdx.y;
    const int blk = blockIdx.x;
    const int tid = threadIdx.x;
    const int n   = blk * TPB + tid;
    const int lane = tid & 31, warp = tid >> 5;

    __shared__ float    sC[KK*DD];
    __shared__ float    sCC[KK];
    __shared__ float    sW[TPB];
    __shared__ float    sAW[KK];
    __shared__ unsigned smask[KK][TPB/32];

    if (first) {
        for (int i = tid; i < KK*DD; i += TPB) sC[i] = g_C[b][i];
        if (tid < KK) sCC[tid] = g_CC[b][tid];
    } else {
        prologue_reduce(rd, b, tid, sC, sCC, sAW);
    }
    __syncthreads();

    float x[DD];
    float xx = 0.f;
    const float4* xp = (const float4*)(E + ((size_t)b*NN + n)*DD);
    #pragma unroll
    for (int i = 0; i < DD/4; i++) {
        float4 v = xp[i];
        x[4*i] = v.x; x[4*i+1] = v.y; x[4*i+2] = v.z; x[4*i+3] = v.w;
        xx += v.x*v.x + v.y*v.y + v.z*v.z + v.w*v.w;
    }

    float dist[KK];
    float mind = 3.4e38f;
    #pragma unroll
    for (int k = 0; k < KK; k++) {
        float a0 = 0.f, a1 = 0.f, a2 = 0.f, a3 = 0.f;
        const float4* cp = (const float4*)(sC + k*DD);
        #pragma unroll
        for (int i = 0; i < DD/4; i++) {
            float4 c4 = cp[i];
            a0 += x[4*i]   * c4.x;
            a1 += x[4*i+1] * c4.y;
            a2 += x[4*i+2] * c4.z;
            a3 += x[4*i+3] * c4.w;
        }
        float dd = sCC[k] + xx - 2.f * ((a0 + a1) + (a2 + a3));
        dist[k] = dd;
        mind = fminf(mind, dd);
    }
    unsigned bits = 0u;
    #pragma unroll
    for (int k = 0; k < KK; k++)
        if (fabsf(dist[k] - mind) < 1e-8f) bits |= (1u << k);
    g_ass[b][n] = bits;
    sW[tid] = expf(LW[(size_t)b*NN + n]);

    #pragma unroll
    for (int k = 0; k < KK; k++) {
        unsigned m = __ballot_sync(0xffffffffu, (bits >> k) & 1u);
        if (lane == 0) smask[k][warp] = m;
    }
    __syncthreads();

    // deterministic accumulation: thread t owns (k = t>>3, dims d0..d0+7)
    const int k  = tid >> 3;
    const int d0 = (tid & 7) * 8;
    float acc[8] = {0,0,0,0,0,0,0,0};
    float wsum = 0.f;
    const float* Eb = E + (((size_t)b*NN + (size_t)blk*TPB)*DD + d0);
    #pragma unroll
    for (int wp = 0; wp < TPB/32; wp++) {
        unsigned m = smask[k][wp];
        while (m) {
            int l = __ffs(m) - 1; m &= m - 1;
            int nn = wp*32 + l;
            float wv = sW[nn];
            const float4* ep = (const float4*)(Eb + (size_t)nn*DD);
            float4 e0 = ep[0], e1 = ep[1];
            acc[0] += wv*e0.x; acc[1] += wv*e0.y; acc[2] += wv*e0.z; acc[3] += wv*e0.w;
            acc[4] += wv*e1.x; acc[5] += wv*e1.y; acc[6] += wv*e1.z; acc[7] += wv*e1.w;
            wsum += wv;
        }
    }
    float* pp = &g_part[wr][b][blk][k*DD + d0];
    ((float4*)pp)[0] = make_float4(acc[0], acc[1], acc[2], acc[3]);
    ((float4*)pp)[1] = make_float4(acc[4], acc[5], acc[6], acc[7]);
    if ((tid & 7) == 0) g_partw[wr][b][blk][k] = wsum;
}

// ---------------- final pass 1: prologue reduce + Dt/obj/rep/ass outputs ----
__global__ __launch_bounds__(TPB) void final1_kernel(const float* __restrict__ E,
                                                     float* __restrict__ out,
                                                     int rd)
{
    const int b   = blockIdx.y;
    const int blk = blockIdx.x;
    const int tid = threadIdx.x;
    const int n   = blk * TPB + tid;

    __shared__ float sC[KK*DD];
    __shared__ float sCC[KK];
    __shared__ float sAW[KK];
    __shared__ unsigned long long srep[KK];
    __shared__ float sred[TPB/32];

    prologue_reduce(rd, b, tid, sC, sCC, sAW);
    if (tid < KK) srep[tid] = 0xFFFFFFFFFFFFFFFFull;
    __syncthreads();

    // block 0 of each batch persists the final C for final2's output
    if (blk == 0) {
        #pragma unroll
        for (int r = 0; r < (KK*DD)/TPB; r++) {
            const int e = r*TPB + tid;
            g_C[b][e] = sC[e];
        }
    }

    float x[DD];
    float xx = 0.f;
    const float4* xp = (const float4*)(E + ((size_t)b*NN + n)*DD);
    #pragma unroll
    for (int i = 0; i < DD/4; i++) {
        float4 v = xp[i];
        x[4*i] = v.x; x[4*i+1] = v.y; x[4*i+2] = v.z; x[4*i+3] = v.w;
        xx += v.x*v.x + v.y*v.y + v.z*v.z + v.w*v.w;
    }

    float dist[KK];
    float mind = 3.4e38f;
    #pragma unroll
    for (int k = 0; k < KK; k++) {
        float a0 = 0.f, a1 = 0.f, a2 = 0.f, a3 = 0.f;
        const float4* cp = (const float4*)(sC + k*DD);
        #pragma unroll
        for (int i = 0; i < DD/4; i++) {
            float4 c4 = cp[i];
            a0 += x[4*i]   * c4.x;
            a1 += x[4*i+1] * c4.y;
            a2 += x[4*i+2] * c4.z;
            a3 += x[4*i+3] * c4.w;
        }
        float dd = sCC[k] + xx - 2.f * ((a0 + a1) + (a2 + a3));
        dist[k] = dd;
        mind = fminf(mind, dd);
    }

    #pragma unroll
    for (int k = 0; k < KK; k++) {
        g_Dt[b][k][n] = dist[k];
        unsigned u = __float_as_uint(dist[k]);
        u = (u & 0x80000000u) ? ~u : (u | 0x80000000u);
        unsigned long long keyv = ((unsigned long long)u << 32) | (unsigned)n;
        atomicMin(&srep[k], keyv);
    }

    // obj partial: fixed-order warp shuffle + in-order warp combine
    float s = mind;
    #pragma unroll
    for (int o = 16; o; o >>= 1) s += __shfl_down_sync(0xffffffffu, s, o);
    if ((tid & 31) == 0) sred[tid >> 5] = s;
    __syncthreads();
    if (tid == 0) {
        float t = 0.f;
        #pragma unroll
        for (int w = 0; w < TPB/32; w++) t += sred[w];
        g_objp[b][blk] = t;
    }
    if (tid < KK) atomicMin(&g_repmin[b][tid], srep[tid]);

    // expand assignment bitmask -> float matrix
    unsigned bits = g_ass[b][n];
    float* ob = out + ((size_t)b*NN + n) * KK;
    #pragma unroll
    for (int k4 = 0; k4 < KK; k4 += 4) {
        float4 v;
        v.x = (bits >> (k4    )) & 1u ? 1.f : 0.f;
        v.y = (bits >> (k4 + 1)) & 1u ? 1.f : 0.f;
        v.z = (bits >> (k4 + 2)) & 1u ? 1.f : 0.f;
        v.w = (bits >> (k4 + 3)) & 1u ? 1.f : 0.f;
        ((float4*)ob)[k4 >> 2] = v;
    }
}

// ---------------- final pass 2: rep, rep_idx, C, obj outputs ----------------
#define F2T 512
__global__ __launch_bounds__(F2T) void final2_kernel(const float* __restrict__ E,
                                                     float* __restrict__ out)
{
    const int b = blockIdx.y, k = blockIdx.x, tid = threadIdx.x;

    __shared__ unsigned smk[F2T];    // 16-bit match masks
    __shared__ int      slist[64];   // ascending-n match indices
    __shared__ int      scount;

    unsigned long long packed = g_repmin[b][k];
    unsigned enc = (unsigned)(packed >> 32);
    unsigned idx = (unsigned)(packed & 0xFFFFFFFFu);
    unsigned u = (enc & 0x80000000u) ? (enc & 0x7FFFFFFFu) : ~enc;
    float mind = __uint_as_float(u);

    // phase 1: each thread scans 16 contiguous distances (coalesced, once)
    {
        const float* Dk = &g_Dt[b][k][tid * 16];
        unsigned m = 0u;
        #pragma unroll
        for (int j = 0; j < 16; j++)
            if (fabsf(Dk[j] - mind) < 1e-8f) m |= (1u << j);
        smk[tid] = m;
    }
    __syncthreads();

    // phase 2: warp 0 compacts set bits into ascending-n index list
    if (tid < 32) {
        unsigned mw[16];
        int cnt = 0;
        #pragma unroll
        for (int j = 0; j < 16; j++) {
            mw[j] = smk[tid*16 + j];
            cnt += __popc(mw[j]);
        }
        int off = cnt;
        #pragma unroll
        for (int o = 1; o < 32; o <<= 1) {
            int v = __shfl_up_sync(0xffffffffu, off, o);
            if ((tid & 31) >= o) off += v;
        }
        int total = __shfl_sync(0xffffffffu, off, 31);
        off -= cnt;
        int pos = off;
        #pragma unroll
        for (int j = 0; j < 16; j++) {
            unsigned m = mw[j];
            while (m) {
                int l2 = __ffs(m) - 1; m &= m - 1;
                if (pos < 64) slist[pos] = (tid*16 + j)*16 + l2;
                pos++;
            }
        }
        if (tid == 31) scount = total;
    }
    __syncthreads();

    if (tid < DD) {
        int c = min(scount, 64);
        float denom = fmaxf((float)scount, 0.001f);
        float s = 0.f;
        for (int t = 0; t < c; t++)
            s += E[((size_t)b*NN + slist[t])*DD + tid];

        const size_t CB = (size_t)BB*NN*KK;
        out[CB + (size_t)(b*KK + k)*DD + tid] = g_C[b][k*DD + tid];
        out[CB + (size_t)BB*KK*DD + (size_t)(b*KK + k)*DD + tid] = s / denom;
        if (tid == 0)
            out[CB + 2*(size_t)BB*KK*DD + b*KK + k] = (float)idx;
        if (tid == 0 && k == 0) {
            float o = 0.f;
            #pragma unroll
            for (int blk = 0; blk < NBLK; blk++) o += g_objp[b][blk];
            out[CB + 2*(size_t)BB*KK*DD + BB*KK + b] = o / (float)NN;
        }
    }
}

// ---------------- launch ----------------------------------------------------
extern "C" void kernel_launch(void* const* d_in, const int* in_sizes, int n_in,
                              void* d_out, int out_size)
{
    const float* E  = (const float*)d_in[0];
    const float* LW = (const float*)d_in[1];
    if (n_in >= 2 && in_sizes[0] == BB*NN) {
        E  = (const float*)d_in[1];
        LW = (const float*)d_in[0];
    }
    float* out = (float*)d_out;

    init_kernel<<<1, 1024>>>(E);
    // t=0: reads g_C (first=1), writes buf 1.
    // t>0: reads buf t&1, writes buf (t&1)^1.  After t=29 -> final in buf 0.
    iter_kernel<<<dim3(NBLK, BB), TPB>>>(E, LW, 0, 1, 1);
    for (int t = 1; t < 30; t++)
        iter_kernel<<<dim3(NBLK, BB), TPB>>>(E, LW, t & 1, (t & 1) ^ 1, 0);
    final1_kernel<<<dim3(NBLK, BB), TPB>>>(E, out, 0);
    final2_kernel<<<dim3(KK, BB), F2T>>>(E, out);
    (void)out_size;
}